// round 14
// baseline (speedup 1.0000x reference)
#include <cuda_runtime.h>
#include <cuda_bf16.h>
#include <cstdint>
#include <cstddef>

#define B_ 4
#define T_ 4096
#define C_ 512
#define CHUNK 64
#define NCHUNK (T_/CHUNK)

// bf16 warp MMA: D(16x8,f32) += A(16x16,row) * B(16x8,col)
__device__ __forceinline__ void mma16816(float* c, const uint32_t* a, const uint32_t* b) {
    asm volatile(
        "mma.sync.aligned.m16n8k16.row.col.f32.bf16.bf16.f32 "
        "{%0,%1,%2,%3}, {%4,%5,%6,%7}, {%8,%9}, {%0,%1,%2,%3};\n"
        : "+f"(c[0]), "+f"(c[1]), "+f"(c[2]), "+f"(c[3])
        : "r"(a[0]), "r"(a[1]), "r"(a[2]), "r"(a[3]), "r"(b[0]), "r"(b[1]));
}
__device__ __forceinline__ void ldsm4(uint32_t* r, uint32_t a) {
    asm volatile("ldmatrix.sync.aligned.m8n8.x4.shared.b16 {%0,%1,%2,%3}, [%4];"
        : "=r"(r[0]), "=r"(r[1]), "=r"(r[2]), "=r"(r[3]) : "r"(a));
}
// A 16x16 tiles (m,k),(m+8,k),(m,k+8),(m+8,k+8); strideHW in halfwords
__device__ __forceinline__ uint32_t addrA(uint32_t base, int row0, int k, int strideHW, int lane) {
    int t = lane >> 3, r = lane & 7;
    return base + (uint32_t)(((row0 + ((t & 1) << 3) + r) * strideHW + k + ((t >> 1) << 3)) * 2);
}
// B (n-major rows) tiles (n,k),(n,k+8),(n+8,k),(n+8,k+8)
__device__ __forceinline__ uint32_t addrB(uint32_t base, int n0, int k, int strideHW, int lane) {
    int t = lane >> 3, r = lane & 7;
    return base + (uint32_t)(((n0 + ((t >> 1) << 3) + r) * strideHW + k + ((t & 1) << 3)) * 2);
}
// B wide-k: tiles (n,k),(n,k+8),(n,k+16),(n,k+24) (n only 8 rows)
__device__ __forceinline__ uint32_t addrBK(uint32_t base, int n0, int k, int strideHW, int lane) {
    int t = lane >> 3, r = lane & 7;
    return base + (uint32_t)(((n0 + r) * strideHW + k + (t << 3)) * 2);
}
__device__ __forceinline__ uint32_t smem_u32(const void* p) {
    uint32_t a;
    asm("{ .reg .u64 t; cvta.to.shared.u64 t, %1; cvt.u32.u64 %0, t; }" : "=r"(a) : "l"(p));
    return a;
}
__device__ __forceinline__ void cpasync16(uint32_t s, const void* g) {
    asm volatile("cp.async.cg.shared.global [%0], [%1], 16;" :: "r"(s), "l"(g));
}
#define CP_COMMIT() asm volatile("cp.async.commit_group;" ::: "memory")
#define CP_WAIT0()  asm volatile("cp.async.wait_group 0;" ::: "memory")
#define CP_WAIT2()  asm volatile("cp.async.wait_group 2;" ::: "memory")

__device__ __forceinline__ void split2(__nv_bfloat16* dh, __nv_bfloat16* dl, float2 v) {
    __nv_bfloat16 h0 = __float2bfloat16(v.x), h1 = __float2bfloat16(v.y);
    __nv_bfloat16 l0 = __float2bfloat16(v.x - __bfloat162float(h0));
    __nv_bfloat16 l1 = __float2bfloat16(v.y - __bfloat162float(h1));
    __nv_bfloat16 hp[2] = {h0, h1}, lp[2] = {l0, l1};
    *(uint32_t*)dh = *(uint32_t*)hp;
    *(uint32_t*)dl = *(uint32_t*)lp;
}

// -------- scratch (__device__ globals) --------
__device__ float g_OL[B_*T_*C_];
__device__ float g_sQ[T_];
__device__ float g_sK[T_];
__device__ float g_SR[NCHUNK];
__device__ __nv_bfloat16 g_Xh[B_*T_*C_];
__device__ __nv_bfloat16 g_Xl[B_*T_*C_];
__device__ __nv_bfloat16 g_Wht[3*C_*C_];
__device__ __nv_bfloat16 g_Wlt[3*C_*C_];
__device__ __nv_bfloat16 g_Qh[B_*T_*C_];   // [b][t][c]
__device__ __nv_bfloat16 g_Ql[B_*T_*C_];
__device__ __nv_bfloat16 g_Kh[B_*T_*C_];
__device__ __nv_bfloat16 g_Kl[B_*T_*C_];
__device__ __nv_bfloat16 g_KTh[B_*C_*T_];  // [b][c][t]
__device__ __nv_bfloat16 g_KTl[B_*C_*T_];
__device__ __nv_bfloat16 g_VTh[B_*C_*T_];
__device__ __nv_bfloat16 g_VTl[B_*C_*T_];

// -------- gamma scales --------
__global__ void scales_kernel() {
    int ch = threadIdx.x;
    if (ch >= NCHUNK) return;
    const float step = 0.03f / 4095.0f;
    float r = 1.0f;
    for (int i = 0; i < CHUNK; ++i) {
        int t = ch * CHUNK + i;
        float g = 0.96f + step * (float)t;
        r *= g;
        g_sQ[t] = r;
        g_sK[t] = 1.0f / r;
    }
    g_SR[ch] = r;
}

// -------- split-bf16 converts --------
__global__ __launch_bounds__(256) void convX_kernel(const float* __restrict__ X) {
    int i = blockIdx.x * 256 + threadIdx.x;
    float4 v = *(const float4*)&X[(size_t)i * 4];
    __nv_bfloat16 h[4], l[4];
    float vv[4] = {v.x, v.y, v.z, v.w};
    #pragma unroll
    for (int j = 0; j < 4; ++j) {
        h[j] = __float2bfloat16(vv[j]);
        l[j] = __float2bfloat16(vv[j] - __bfloat162float(h[j]));
    }
    *(uint2*)&g_Xh[(size_t)i * 4] = *(uint2*)h;
    *(uint2*)&g_Xl[(size_t)i * 4] = *(uint2*)l;
}

__global__ __launch_bounds__(256) void convW_kernel(
        const float* __restrict__ W0, const float* __restrict__ W1,
        const float* __restrict__ W2) {
    __shared__ float tile[32][33];
    const int w = blockIdx.z;
    const float* W = (w == 0) ? W0 : ((w == 1) ? W1 : W2);
    const int k0 = blockIdx.y * 32, n0 = blockIdx.x * 32;
    const int tx = threadIdx.x & 31, ty = threadIdx.x >> 5;
    #pragma unroll
    for (int i = 0; i < 32; i += 8)
        tile[ty + i][tx] = W[(size_t)(k0 + ty + i) * C_ + n0 + tx];
    __syncthreads();
    #pragma unroll
    for (int i = 0; i < 32; i += 8) {
        int nl = ty + i;
        float v = tile[tx][nl];
        __nv_bfloat16 h = __float2bfloat16(v);
        __nv_bfloat16 l = __float2bfloat16(v - __bfloat162float(h));
        size_t o = ((size_t)w * C_ + (n0 + nl)) * C_ + k0 + tx;
        g_Wht[o] = h;
        g_Wlt[o] = l;
    }
}

// -------- HMMA projection (unchanged, passing) --------
#define SA 40
#define TILE_HW (128 * SA)
#define PJ_TB   (TILE_HW * 2)
#define PJ_BUF  (4 * PJ_TB)
#define PJ_TRS  136
__global__ __launch_bounds__(256, 2) void projmma_kernel(
        const float* __restrict__ bQ, const float* __restrict__ bK,
        const float* __restrict__ bV) {
    extern __shared__ char shp[];
    const uint32_t sbase = smem_u32(shp);

    const int tid = threadIdx.x;
    const int w = tid >> 5, lane = tid & 31;
    const int g = lane >> 2, t4 = lane & 3;
    const int wm = w >> 2, wn = w & 3;
    const int which = blockIdx.x >> 2;
    const int n0 = (blockIdx.x & 3) * 128;
    const int m0 = blockIdx.y * 128;
    const float* bias = (which == 0) ? bQ : ((which == 1) ? bK : bV);

    const __nv_bfloat16* srcs[4] = {
        g_Xh + (size_t)m0 * C_, g_Xl + (size_t)m0 * C_,
        g_Wht + ((size_t)which * C_ + n0) * C_, g_Wlt + ((size_t)which * C_ + n0) * C_ };

    auto stage = [&](int bufi, int ck) {
        uint32_t base = sbase + (uint32_t)bufi * PJ_BUF;
        const int k0 = ck * 32;
        #pragma unroll
        for (int a = 0; a < 4; ++a) {
            #pragma unroll
            for (int j = 0; j < 2; ++j) {
                int u = tid + j * 256;
                int r = u >> 2, cg = u & 3;
                cpasync16(base + a * PJ_TB + r * 80 + cg * 16,
                          srcs[a] + (size_t)r * C_ + k0 + cg * 8);
            }
        }
    };

    float acc[4][4][4];
    #pragma unroll
    for (int i = 0; i < 4; ++i)
        #pragma unroll
        for (int j = 0; j < 4; ++j)
            #pragma unroll
            for (int r = 0; r < 4; ++r) acc[i][j][r] = 0.f;

    stage(0, 0);
    CP_COMMIT(); CP_WAIT0();
    __syncthreads();

    for (int ck = 0; ck < 16; ++ck) {
        const int buf = ck & 1;
        if (ck + 1 < 16) stage(buf ^ 1, ck + 1);
        CP_COMMIT();

        const uint32_t bAh = sbase + buf * PJ_BUF;
        const uint32_t bAl = bAh + PJ_TB;
        const uint32_t bBh = bAh + 2 * PJ_TB;
        const uint32_t bBl = bAh + 3 * PJ_TB;

        #pragma unroll
        for (int kk = 0; kk < 32; kk += 16) {
            uint32_t bhf[4], blf[4], bhf2[4], blf2[4];
            ldsm4(bhf,  addrB(bBh, wn * 32,      kk, SA, lane));
            ldsm4(bhf2, addrB(bBh, wn * 32 + 16, kk, SA, lane));
            ldsm4(blf,  addrB(bBl, wn * 32,      kk, SA, lane));
            ldsm4(blf2, addrB(bBl, wn * 32 + 16, kk, SA, lane));
            #pragma unroll
            for (int mf = 0; mf < 4; ++mf) {
                uint32_t ah[4], al[4];
                ldsm4(ah, addrA(bAh, wm * 64 + mf * 16, kk, SA, lane));
                ldsm4(al, addrA(bAl, wm * 64 + mf * 16, kk, SA, lane));
                mma16816(acc[mf][0], ah, bhf);
                mma16816(acc[mf][1], ah, bhf + 2);
                mma16816(acc[mf][2], ah, bhf2);
                mma16816(acc[mf][3], ah, bhf2 + 2);
                mma16816(acc[mf][0], ah, blf);
                mma16816(acc[mf][1], ah, blf + 2);
                mma16816(acc[mf][2], ah, blf2);
                mma16816(acc[mf][3], ah, blf2 + 2);
                mma16816(acc[mf][0], al, bhf);
                mma16816(acc[mf][1], al, bhf + 2);
                mma16816(acc[mf][2], al, bhf2);
                mma16816(acc[mf][3], al, bhf2 + 2);
            }
        }
        CP_WAIT0();
        __syncthreads();
    }

    __nv_bfloat16* Th = (__nv_bfloat16*)shp;
    __nv_bfloat16* Tl = (__nv_bfloat16*)(shp + 128 * PJ_TRS * 2);

    #pragma unroll
    for (int mf = 0; mf < 4; ++mf) {
        int m = m0 + wm * 64 + mf * 16 + g;
        int tA = m & (T_ - 1);
        int tB = (m + 8) & (T_ - 1);
        float sA = (which == 0) ? g_sQ[tA] : ((which == 1) ? g_sK[tA] : 1.0f);
        float sB = (which == 0) ? g_sQ[tB] : ((which == 1) ? g_sK[tB] : 1.0f);
        #pragma unroll
        for (int nf = 0; nf < 4; ++nf) {
            int nl = wn * 32 + nf * 8 + 2 * t4;
            int n = n0 + nl;
            float2 bb = *(const float2*)&bias[n];
            float2 o0 = make_float2((acc[mf][nf][0] + bb.x) * sA,
                                    (acc[mf][nf][1] + bb.y) * sA);
            float2 o1 = make_float2((acc[mf][nf][2] + bb.x) * sB,
                                    (acc[mf][nf][3] + bb.y) * sB);
            size_t i0 = (size_t)m * C_ + n, i1 = (size_t)(m + 8) * C_ + n;
            if (which == 0) {
                split2(&g_Qh[i0], &g_Ql[i0], o0);
                split2(&g_Qh[i1], &g_Ql[i1], o1);
            } else {
                int ml = wm * 64 + mf * 16 + g;
                split2(&Th[ml * PJ_TRS + nl], &Tl[ml * PJ_TRS + nl], o0);
                split2(&Th[(ml + 8) * PJ_TRS + nl], &Tl[(ml + 8) * PJ_TRS + nl], o1);
                if (which == 1) {
                    split2(&g_Kh[i0], &g_Kl[i0], o0);
                    split2(&g_Kh[i1], &g_Kl[i1], o1);
                }
            }
        }
    }

    if (which != 0) {
        __syncthreads();
        __nv_bfloat16* dsth = (which == 1) ? g_KTh : g_VTh;
        __nv_bfloat16* dstl = (which == 1) ? g_KTl : g_VTl;
        const size_t bofs = (size_t)(m0 >> 12) * C_ * T_;
        const int tbase = m0 & (T_ - 1);
        const int cl = tid >> 1, seg = tid & 1;
        #pragma unroll
        for (int u = 0; u < 16; ++u) {
            int tl = seg * 64 + u * 4;
            __nv_bfloat16 hp[4], lp[4];
            #pragma unroll
            for (int e = 0; e < 4; ++e) {
                hp[e] = Th[(tl + e) * PJ_TRS + cl];
                lp[e] = Tl[(tl + e) * PJ_TRS + cl];
            }
            size_t o = bofs + (size_t)(n0 + cl) * T_ + tbase + tl;
            *(uint2*)&dsth[o] = *(uint2*)hp;
            *(uint2*)&dstl[o] = *(uint2*)lp;
        }
    }
}

// -------- local masked attention (unchanged, passing) --------
#define L_TILE 9216
#define L_BUF  (4 * L_TILE)
#define L_ASH  (2 * L_BUF)
#define L_ASL  (L_ASH + L_TILE)
#define L_SMEM (L_ASL + L_TILE)
__global__ __launch_bounds__(256, 2) void localmma_kernel() {
    extern __shared__ char shl[];
    const uint32_t sbase = smem_u32(shl);
    __nv_bfloat16* Ash = (__nv_bfloat16*)(shl + L_ASH);
    __nv_bfloat16* Asl = (__nv_bfloat16*)(shl + L_ASL);
    const uint32_t aAsh = sbase + L_ASH, aAsl = sbase + L_ASL;

    const int tid = threadIdx.x;
    const int w = tid >> 5, lane = tid & 31;
    const int g = lane >> 2, t4 = lane & 3;
    const int wm = w >> 2, wn = w & 3;
    const int b = blockIdx.x >> 6;
    const int ch = blockIdx.x & 63;
    const size_t rowbase = (size_t)b * T_ + (size_t)ch * CHUNK;

    const __nv_bfloat16* qkSrc[4] = {
        g_Qh + rowbase * C_, g_Ql + rowbase * C_,
        g_Kh + rowbase * C_, g_Kl + rowbase * C_ };
    const __nv_bfloat16* VThb = g_VTh + (size_t)b * C_ * T_;
    const __nv_bfloat16* VTlb = g_VTl + (size_t)b * C_ * T_;

    auto stage_qk = [&](int bufi, int ck2) {
        uint32_t base = sbase + (uint32_t)bufi * L_BUF;
        #pragma unroll
        for (int a = 0; a < 4; ++a) {
            #pragma unroll
            for (int j = 0; j < 2; ++j) {
                int u = tid + j * 256;
                int row = u >> 3, c8 = u & 7;
                cpasync16(base + a * L_TILE + row * 144 + c8 * 16,
                          qkSrc[a] + (size_t)row * C_ + ck2 * 64 + c8 * 8);
            }
        }
    };
    auto stage_vt = [&](int bufi, int dt) {
        uint32_t base = sbase + (uint32_t)bufi * L_BUF;
        #pragma unroll
        for (int hl = 0; hl < 2; ++hl) {
            const __nv_bfloat16* src = hl ? VTlb : VThb;
            #pragma unroll
            for (int j = 0; j < 4; ++j) {
                int u = tid + j * 256;
                int row = u >> 3, c8 = u & 7;
                cpasync16(base + hl * (2 * L_TILE) + row * 144 + c8 * 16,
                          src + (size_t)(dt * 128 + row) * T_ + ch * CHUNK + c8 * 8);
            }
        }
    };

    float acc[2][2][4];
    #pragma unroll
    for (int i = 0; i < 2; ++i)
        #pragma unroll
        for (int j = 0; j < 2; ++j)
            #pragma unroll
            for (int r = 0; r < 4; ++r) acc[i][j][r] = 0.f;

    stage_qk(0, 0);
    CP_COMMIT(); CP_WAIT0();
    __syncthreads();

    for (int ck2 = 0; ck2 < 8; ++ck2) {
        const int buf = ck2 & 1;
        if (ck2 + 1 < 8) stage_qk(buf ^ 1, ck2 + 1);
        CP_COMMIT();
        const uint32_t bQh = sbase + buf * L_BUF;
        const uint32_t bQl = bQh + L_TILE;
        const uint32_t bKh = bQh + 2 * L_TILE;
        const uint32_t bKl = bQh + 3 * L_TILE;
        #pragma unroll
        for (int kk = 0; kk < 64; kk += 16) {
            uint32_t bh[4], bl[4];
            ldsm4(bh, addrB(bKh, wn * 16, kk, 72, lane));
            ldsm4(bl, addrB(bKl, wn * 16, kk, 72, lane));
            uint32_t ah0[4], al0[4], ah1[4], al1[4];
            ldsm4(ah0, addrA(bQh, wm * 32,      kk, 72, lane));
            ldsm4(al0, addrA(bQl, wm * 32,      kk, 72, lane));
            ldsm4(ah1, addrA(bQh, wm * 32 + 16, kk, 72, lane));
            ldsm4(al1, addrA(bQl, wm * 32 + 16, kk, 72, lane));
            mma16816(acc[0][0], ah0, bh);
            mma16816(acc[0][1], ah0, bh + 2);
            mma16816(acc[1][0], ah1, bh);
            mma16816(acc[1][1], ah1, bh + 2);
            mma16816(acc[0][0], ah0, bl);
            mma16816(acc[0][1], ah0, bl + 2);
            mma16816(acc[1][0], ah1, bl);
            mma16816(acc[1][1], ah1, bl + 2);
            mma16816(acc[0][0], al0, bh);
            mma16816(acc[0][1], al0, bh + 2);
            mma16816(acc[1][0], al1, bh);
            mma16816(acc[1][1], al1, bh + 2);
        }
        CP_WAIT0();
        __syncthreads();
    }

    #pragma unroll
    for (int mf = 0; mf < 2; ++mf) {
        #pragma unroll
        for (int nf = 0; nf < 2; ++nf) {
            int t0r = wm * 32 + mf * 16 + g;
            int s0 = wn * 16 + nf * 8 + 2 * t4;
            #pragma unroll
            for (int e = 0; e < 4; ++e) {
                int tt = t0r + (e >> 1) * 8;
                int ss = s0 + (e & 1);
                float v = (ss <= tt) ? acc[mf][nf][e] : 0.f;
                __nv_bfloat16 h = __float2bfloat16(v);
                Ash[tt * 72 + ss] = h;
                Asl[tt * 72 + ss] = __float2bfloat16(v - __bfloat162float(h));
            }
        }
    }
    __syncthreads();

    stage_vt(0, 0);
    CP_COMMIT(); CP_WAIT0();
    __syncthreads();

    for (int dt = 0; dt < 4; ++dt) {
        const int buf = dt & 1;
        if (dt + 1 < 4) stage_vt(buf ^ 1, dt + 1);
        CP_COMMIT();
        const uint32_t bVh = sbase + buf * L_BUF;
        const uint32_t bVl = bVh + 2 * L_TILE;

        float acc2[2][4][4];
        #pragma unroll
        for (int i = 0; i < 2; ++i)
            #pragma unroll
            for (int j = 0; j < 4; ++j)
                #pragma unroll
                for (int r = 0; r < 4; ++r) acc2[i][j][r] = 0.f;

        #pragma unroll
        for (int kk = 0; kk < 64; kk += 16) {
            uint32_t bh[4], bl[4], bh2[4], bl2[4];
            ldsm4(bh,  addrB(bVh, wn * 32,      kk, 72, lane));
            ldsm4(bh2, addrB(bVh, wn * 32 + 16, kk, 72, lane));
            ldsm4(bl,  addrB(bVl, wn * 32,      kk, 72, lane));
            ldsm4(bl2, addrB(bVl, wn * 32 + 16, kk, 72, lane));
            #pragma unroll
            for (int mf = 0; mf < 2; ++mf) {
                uint32_t ah[4], al[4];
                ldsm4(ah, addrA(aAsh, wm * 32 + mf * 16, kk, 72, lane));
                ldsm4(al, addrA(aAsl, wm * 32 + mf * 16, kk, 72, lane));
                mma16816(acc2[mf][0], ah, bh);
                mma16816(acc2[mf][1], ah, bh + 2);
                mma16816(acc2[mf][2], ah, bh2);
                mma16816(acc2[mf][3], ah, bh2 + 2);
                mma16816(acc2[mf][0], ah, bl);
                mma16816(acc2[mf][1], ah, bl + 2);
                mma16816(acc2[mf][2], ah, bl2);
                mma16816(acc2[mf][3], ah, bl2 + 2);
                mma16816(acc2[mf][0], al, bh);
                mma16816(acc2[mf][1], al, bh + 2);
                mma16816(acc2[mf][2], al, bh2);
                mma16816(acc2[mf][3], al, bh2 + 2);
            }
        }

        #pragma unroll
        for (int mf = 0; mf < 2; ++mf) {
            int tt = wm * 32 + mf * 16 + g;
            #pragma unroll
            for (int nf = 0; nf < 4; ++nf) {
                int d = dt * 128 + wn * 32 + nf * 8 + 2 * t4;
                *(float2*)&g_OL[(rowbase + tt) * C_ + d] =
                    make_float2(acc2[mf][nf][0], acc2[mf][nf][1]);
                *(float2*)&g_OL[(rowbase + tt + 8) * C_ + d] =
                    make_float2(acc2[mf][nf][2], acc2[mf][nf][3]);
            }
        }
        CP_WAIT0();
        __syncthreads();
    }
}

// ---------------- scan v8: 3-deep cp.async pipeline, prefetch distance 2 ----------------
// 128 CTAs (b, 16-d slab), 512 threads. 8 phases/chunk:
//   p0..p3: GEMM1 q-tiles [64t x 128c]  (warp pairs split 64-k each)
//   p4..p7: GEMM2 k-tiles [128c x 64t]  (warp = 16c x 8d tile)
#define S8_SH    0
#define S8_SL    16640
#define S8_STG   33280
#define S8_BUF   36864
#define S8_VT    (S8_STG + 3 * S8_BUF)       // 143872
#define S8_RED   (S8_VT + 4608)              // 148480
#define S8_SMEM  (S8_RED + 4096)             // 152576

__global__ __launch_bounds__(512) void scan8_kernel(
        float* __restrict__ O, float* __restrict__ Sout, int writeS) {
    extern __shared__ char s8[];
    __nv_bfloat16* SHh = (__nv_bfloat16*)(s8 + S8_SH);
    __nv_bfloat16* SHl = (__nv_bfloat16*)(s8 + S8_SL);
    float* RED = (float*)(s8 + S8_RED);
    const uint32_t sbase = smem_u32(s8);
    const uint32_t aSHh = sbase + S8_SH, aSHl = sbase + S8_SL;

    const int tid = threadIdx.x;
    const int w = tid >> 5, lane = tid & 31;
    const int g = lane >> 2, t4 = lane & 3;
    // GEMM1: 16 warps = 8 output tiles (mg x ng) x 2 k-halves
    const int w8 = w & 7, khalf = w >> 3;
    const int mg = w8 >> 1, ng = w8 & 1;
    // GEMM2: 16 warps = 8 c-groups x 2 d-halves
    const int wc = w >> 1, wd = w & 1;
    const int b = blockIdx.x >> 5;
    const int d0 = (blockIdx.x & 31) * 16;

    const __nv_bfloat16* Qh  = g_Qh  + (size_t)b * T_ * C_;
    const __nv_bfloat16* Ql  = g_Ql  + (size_t)b * T_ * C_;
    const __nv_bfloat16* KTh = g_KTh + (size_t)b * C_ * T_;
    const __nv_bfloat16* KTl = g_KTl + (size_t)b * C_ * T_;
    const __nv_bfloat16* VTh = g_VTh + (size_t)b * C_ * T_;
    const __nv_bfloat16* VTl = g_VTl + (size_t)b * C_ * T_;
    const float* OLb = g_OL + (size_t)b * T_ * C_;
    float* Ob = O + (size_t)b * T_ * C_;

    for (int i = tid; i < 16 * 520 / 2; i += 512) {
        ((uint32_t*)SHh)[i] = 0u;
        ((uint32_t*)SHl)[i] = 0u;
    }

    // q-tile [64 rows][128c], stride 136 hw (272 B); h at +0, l at +18432
    auto stage_q = [&](int bi, size_t rb, int qp) {
        uint32_t base = sbase + S8_STG + (uint32_t)bi * S8_BUF;
        #pragma unroll
        for (int j = 0; j < 4; ++j) {
            int u = tid + 512 * j;
            int hl = u >> 10, ur = u & 1023;
            int row = ur >> 4, c16 = ur & 15;
            const __nv_bfloat16* src = hl ? Ql : Qh;
            cpasync16(base + (uint32_t)hl * 18432 + row * 272 + c16 * 16,
                      src + (rb + row) * C_ + qp * 128 + c16 * 8);
        }
    };
    // k-tile [128 c-rows][64 t], stride 72 hw (144 B)
    auto stage_k = [&](int bi, size_t rb, int kp) {
        uint32_t base = sbase + S8_STG + (uint32_t)bi * S8_BUF;
        #pragma unroll
        for (int j = 0; j < 4; ++j) {
            int u = tid + 512 * j;
            int hl = u >> 10, ur = u & 1023;
            int row = ur >> 3, c8 = ur & 7;
            const __nv_bfloat16* src = hl ? KTl : KTh;
            cpasync16(base + (uint32_t)hl * 18432 + row * 144 + c8 * 16,
                      src + (size_t)(kp * 128 + row) * T_ + rb + c8 * 8);
        }
    };
    auto stage_vt = [&](size_t rb) {
        if (tid < 256) {
            int hl = tid >> 7, ur = tid & 127;
            int row = ur >> 3, c8 = ur & 7;
            const __nv_bfloat16* src = hl ? VTl : VTh;
            cpasync16(sbase + S8_VT + hl * 2304 + row * 144 + c8 * 16,
                      src + (size_t)(d0 + row) * T_ + rb + c8 * 8);
        }
    };

    // prologue: stage tiles (0,0) and (0,1) as two groups
    stage_q(0, 0, 0); CP_COMMIT();
    stage_q(1, 0, 1); CP_COMMIT();

    float acc1a[4] = {0.f, 0.f, 0.f, 0.f};
    float acc1b[4] = {0.f, 0.f, 0.f, 0.f};
    float2 ol0 = make_float2(0.f, 0.f), ol1 = make_float2(0.f, 0.f);
    float Sreg[16];
    #pragma unroll
    for (int i = 0; i < 16; ++i) Sreg[i] = 0.f;

    int bcur = 0;
    for (int ch = 0; ch < NCHUNK; ++ch) {
        const size_t crow = (size_t)ch * CHUNK;
        const float R = __ldg(&g_SR[ch]);

        for (int p = 0; p < 8; ++p) {
            // prefetch tile for phase p+2 into buffer (bcur+2)%3
            {
                int np = p + 2;
                size_t prb = crow;
                int pp = np;
                if (np >= 8) {
                    pp = np - 8;
                    prb = (ch + 1 < NCHUNK) ? crow + CHUNK : crow;
                }
                int tb = bcur + 2; if (tb >= 3) tb -= 3;
                if (pp < 4) stage_q(tb, prb, pp);
                else        stage_k(tb, prb, pp - 4);
                if (pp == 4) stage_vt(prb);   // VT for this chunk, ready by p4
            }
            CP_COMMIT();
            CP_WAIT2();          // phase p's tile fully arrived
            __syncthreads();

            if (p == 0) {
                ol0 = __ldg((const float2*)&OLb[(crow + mg * 16 + g) * C_ + d0 + ng * 8 + 2 * t4]);
                ol1 = __ldg((const float2*)&OLb[(crow + mg * 16 + g + 8) * C_ + d0 + ng * 8 + 2 * t4]);
            }

            const uint32_t bufb = sbase + S8_STG + (uint32_t)bcur * S8_BUF;
            if (p < 4) {
                // GEMM1: cross += Q~[64][128c] . S[128c][16d] ; warp (mg,ng,khalf)
                const uint32_t bQsh = bufb, bQsl = bufb + 18432;
                #pragma unroll
                for (int kk = 0; kk < 64; kk += 32) {
                    const int kloc = khalf * 64 + kk;          // within 128-c tile
                    const int kglb = p * 128 + kloc;           // S column index
                    uint32_t bh4[4], bl4[4];
                    ldsm4(bh4, addrBK(aSHh, ng * 8, kglb, 520, lane));
                    ldsm4(bl4, addrBK(aSHl, ng * 8, kglb, 520, lane));
                    uint32_t ah0[4], al0[4], ah1[4], al1[4];
                    ldsm4(ah0, addrA(bQsh, mg * 16, kloc,      136, lane));
                    ldsm4(al0, addrA(bQsl, mg * 16, kloc,      136, lane));
                    ldsm4(ah1, addrA(bQsh, mg * 16, kloc + 16, 136, lane));
                    ldsm4(al1, addrA(bQsl, mg * 16, kloc + 16, 136, lane));
                    mma16816(acc1a, ah0, bh4);
                    mma16816(acc1b, ah1, bh4 + 2);
                    mma16816(acc1a, ah0, bl4);
                    mma16816(acc1b, ah1, bl4 + 2);
                    mma16816(acc1a, al0, bh4);
                    mma16816(acc1b, al1, bh4 + 2);
                }
                if (p == 3 && khalf == 1) {
                    *(float4*)&RED[(w8 * 32 + lane) * 4] =
                        make_float4(acc1a[0] + acc1b[0], acc1a[1] + acc1b[1],
                                    acc1a[2] + acc1b[2], acc1a[3] + acc1b[3]);
                    #pragma unroll
                    for (int r = 0; r < 4; ++r) { acc1a[r] = 0.f; acc1b[r] = 0.f; }
                }
            } else {
                if (p == 4 && khalf == 0) {
                    float4 pr = *(const float4*)&RED[(w8 * 32 + lane) * 4];
                    const int trow = (int)crow + mg * 16 + g;
                    const int d = d0 + ng * 8 + 2 * t4;
                    *(float2*)&Ob[(size_t)trow * C_ + d] =
                        make_float2(tanhf(acc1a[0] + acc1b[0] + pr.x + ol0.x),
                                    tanhf(acc1a[1] + acc1b[1] + pr.y + ol0.y));
                    *(float2*)&Ob[(size_t)(trow + 8) * C_ + d] =
                        make_float2(tanhf(acc1a[2] + acc1b[2] + pr.z + ol1.x),
                                    tanhf(acc1a[3] + acc1b[3] + pr.w + ol1.y));
                    #pragma unroll
                    for (int r = 0; r < 4; ++r) { acc1a[r] = 0.f; acc1b[r] = 0.f; }
                }
                // GEMM2: warp (wc, wd): A = K^T rows [wc*16..+16], B = V^T rows [wd*8..+8]
                const int kp = p - 4;
                const uint32_t bKsh = bufb, bKsl = bufb + 18432;
                const uint32_t bVth = sbase + S8_VT;
                const uint32_t bVtl = bVth + 2304;
                float acc2[4] = {0.f, 0.f, 0.f, 0.f};
                #pragma unroll
                for (int kk = 0; kk < 64; kk += 16) {
                    uint32_t bh[4], bl[4];
                    ldsm4(bh, addrB(bVth, wd * 8, kk, 72, lane));   // use tiles 0,1
                    ldsm4(bl, addrB(bVtl, wd * 8, kk, 72, lane));
                    uint32_t ah[4], al[4];
                    ldsm4(ah, addrA(bKsh, wc * 16, kk, 72, lane));
                    ldsm4(al, addrA(bKsl, wc * 16, kk, 72, lane));
                    mma16816(acc2, ah, bh);
                    mma16816(acc2, ah, bl);
                    mma16816(acc2, al, bh);
                }
                // S = (S + delta) * R; fp32 master in regs, bf16 h/l mirror to smem
                #pragma unroll
                for (int e = 0; e < 4; ++e) {
                    int idx = kp * 4 + e;
                    int c = kp * 128 + wc * 16 + g + (e >> 1) * 8;
                    int d = wd * 8 + 2 * t4 + (e & 1);
                    int ad = d * 520 + c;
                    float v = (Sreg[idx] + acc2[e]) * R;
                    Sreg[idx] = v;
                    __nv_bfloat16 h = __float2bfloat16(v);
                    SHh[ad] = h;
                    SHl[ad] = __float2bfloat16(v - __bfloat162float(h));
                }
            }
            ++bcur; if (bcur >= 3) bcur -= 3;
        }
    }

    __syncthreads();
    if (writeS) {
        for (int idx = tid; idx < C_ * 16; idx += 512) {
            int c = idx >> 4, dl = idx & 15;
            Sout[((size_t)b * C_ + c) * C_ + d0 + dl] =
                __bfloat162float(SHh[dl * 520 + c]) + __bfloat162float(SHl[dl * 520 + c]);
        }
    }
}

extern "C" void kernel_launch(void* const* d_in, const int* in_sizes, int n_in,
                              void* d_out, int out_size) {
    const float* X  = (const float*)d_in[0];
    // d_in[1] = S_n (ignored; reference resets state to zero)
    const float* WQ = (const float*)d_in[2];
    const float* bQ = (const float*)d_in[3];
    const float* WK = (const float*)d_in[4];
    const float* bK = (const float*)d_in[5];
    const float* WV = (const float*)d_in[6];
    const float* bV = (const float*)d_in[7];
    float* out = (float*)d_out;

    const int oElems = B_ * T_ * C_;
    const int sElems = B_ * C_ * C_;
    int writeS = (out_size >= oElems + sElems) ? 1 : 0;
    float* Sout = out + oElems;

    const int smP = 2 * PJ_BUF;
    cudaFuncSetAttribute(projmma_kernel, cudaFuncAttributeMaxDynamicSharedMemorySize, smP);
    cudaFuncSetAttribute(localmma_kernel, cudaFuncAttributeMaxDynamicSharedMemorySize, L_SMEM);
    cudaFuncSetAttribute(scan8_kernel, cudaFuncAttributeMaxDynamicSharedMemorySize, S8_SMEM);

    scales_kernel<<<1, NCHUNK>>>();
    convX_kernel<<<(B_ * T_ * C_) / 1024, 256>>>(X);
    dim3 wg(16, 16, 3);
    convW_kernel<<<wg, 256>>>(WQ, WK, WV);
    dim3 pg(12, (B_ * T_) / 128);
    projmma_kernel<<<pg, 256, smP>>>(bQ, bK, bV);
    localmma_kernel<<<B_ * NCHUNK, 256, L_SMEM>>>();
    scan8_kernel<<<B_ * 32, 512, S8_SMEM>>>(out, Sout, writeS);
}

// round 15
// speedup vs baseline: 1.1221x; 1.1221x over previous
#include <cuda_runtime.h>
#include <cuda_bf16.h>
#include <cstdint>
#include <cstddef>

#define B_ 4
#define T_ 4096
#define C_ 512
#define CHUNK 64
#define NCHUNK (T_/CHUNK)

// bf16 warp MMA: D(16x8,f32) += A(16x16,row) * B(16x8,col)
__device__ __forceinline__ void mma16816(float* c, const uint32_t* a, const uint32_t* b) {
    asm volatile(
        "mma.sync.aligned.m16n8k16.row.col.f32.bf16.bf16.f32 "
        "{%0,%1,%2,%3}, {%4,%5,%6,%7}, {%8,%9}, {%0,%1,%2,%3};\n"
        : "+f"(c[0]), "+f"(c[1]), "+f"(c[2]), "+f"(c[3])
        : "r"(a[0]), "r"(a[1]), "r"(a[2]), "r"(a[3]), "r"(b[0]), "r"(b[1]));
}
__device__ __forceinline__ void ldsm4(uint32_t* r, uint32_t a) {
    asm volatile("ldmatrix.sync.aligned.m8n8.x4.shared.b16 {%0,%1,%2,%3}, [%4];"
        : "=r"(r[0]), "=r"(r[1]), "=r"(r[2]), "=r"(r[3]) : "r"(a));
}
// A 16x16 tiles (m,k),(m+8,k),(m,k+8),(m+8,k+8); strideHW in halfwords
__device__ __forceinline__ uint32_t addrA(uint32_t base, int row0, int k, int strideHW, int lane) {
    int t = lane >> 3, r = lane & 7;
    return base + (uint32_t)(((row0 + ((t & 1) << 3) + r) * strideHW + k + ((t >> 1) << 3)) * 2);
}
// B (n-major rows) tiles (n,k),(n,k+8),(n+8,k),(n+8,k+8)
__device__ __forceinline__ uint32_t addrB(uint32_t base, int n0, int k, int strideHW, int lane) {
    int t = lane >> 3, r = lane & 7;
    return base + (uint32_t)(((n0 + ((t >> 1) << 3) + r) * strideHW + k + ((t & 1) << 3)) * 2);
}
// B wide-k: tiles (n,k),(n,k+8),(n,k+16),(n,k+24) (n only 8 rows)
__device__ __forceinline__ uint32_t addrBK(uint32_t base, int n0, int k, int strideHW, int lane) {
    int t = lane >> 3, r = lane & 7;
    return base + (uint32_t)(((n0 + r) * strideHW + k + (t << 3)) * 2);
}
__device__ __forceinline__ uint32_t smem_u32(const void* p) {
    uint32_t a;
    asm("{ .reg .u64 t; cvta.to.shared.u64 t, %1; cvt.u32.u64 %0, t; }" : "=r"(a) : "l"(p));
    return a;
}
__device__ __forceinline__ void cpasync16(uint32_t s, const void* g) {
    asm volatile("cp.async.cg.shared.global [%0], [%1], 16;" :: "r"(s), "l"(g));
}
#define CP_COMMIT() asm volatile("cp.async.commit_group;" ::: "memory")
#define CP_WAIT0()  asm volatile("cp.async.wait_group 0;" ::: "memory")

__device__ __forceinline__ void split2(__nv_bfloat16* dh, __nv_bfloat16* dl, float2 v) {
    __nv_bfloat16 h0 = __float2bfloat16(v.x), h1 = __float2bfloat16(v.y);
    __nv_bfloat16 l0 = __float2bfloat16(v.x - __bfloat162float(h0));
    __nv_bfloat16 l1 = __float2bfloat16(v.y - __bfloat162float(h1));
    __nv_bfloat16 hp[2] = {h0, h1}, lp[2] = {l0, l1};
    *(uint32_t*)dh = *(uint32_t*)hp;
    *(uint32_t*)dl = *(uint32_t*)lp;
}

// -------- scratch (__device__ globals) --------
__device__ float g_OL[B_*T_*C_];
__device__ float g_sQ[T_];
__device__ float g_sK[T_];
__device__ float g_SR[NCHUNK];
__device__ __nv_bfloat16 g_Xh[B_*T_*C_];
__device__ __nv_bfloat16 g_Xl[B_*T_*C_];
__device__ __nv_bfloat16 g_Wht[3*C_*C_];
__device__ __nv_bfloat16 g_Wlt[3*C_*C_];
__device__ __nv_bfloat16 g_Qh[B_*T_*C_];   // [b][t][c]
__device__ __nv_bfloat16 g_Ql[B_*T_*C_];
__device__ __nv_bfloat16 g_Kh[B_*T_*C_];
__device__ __nv_bfloat16 g_Kl[B_*T_*C_];
__device__ __nv_bfloat16 g_KTh[B_*C_*T_];  // [b][c][t]
__device__ __nv_bfloat16 g_KTl[B_*C_*T_];
__device__ __nv_bfloat16 g_VTh[B_*C_*T_];
__device__ __nv_bfloat16 g_VTl[B_*C_*T_];

// -------- fused prep: convX (blocks [0,8192)) + convW ([8192,8960)) + scales (8960) --------
__global__ __launch_bounds__(256) void prep_kernel(
        const float* __restrict__ X,
        const float* __restrict__ W0, const float* __restrict__ W1,
        const float* __restrict__ W2) {
    const int blk = blockIdx.x;
    if (blk < 8192) {
        // convX: one float4 per thread
        int i = blk * 256 + threadIdx.x;
        float4 v = *(const float4*)&X[(size_t)i * 4];
        __nv_bfloat16 h[4], l[4];
        float vv[4] = {v.x, v.y, v.z, v.w};
        #pragma unroll
        for (int j = 0; j < 4; ++j) {
            h[j] = __float2bfloat16(vv[j]);
            l[j] = __float2bfloat16(vv[j] - __bfloat162float(h[j]));
        }
        *(uint2*)&g_Xh[(size_t)i * 4] = *(uint2*)h;
        *(uint2*)&g_Xl[(size_t)i * 4] = *(uint2*)l;
    } else if (blk < 8960) {
        // convW: 32x32 transpose tile
        __shared__ float tile[32][33];
        int wIdx = blk - 8192;
        const int w = wIdx >> 8;              // 0..2
        int rem = wIdx & 255;
        const int k0 = (rem >> 4) * 32, n0 = (rem & 15) * 32;
        const float* W = (w == 0) ? W0 : ((w == 1) ? W1 : W2);
        const int tx = threadIdx.x & 31, ty = threadIdx.x >> 5;
        #pragma unroll
        for (int i = 0; i < 32; i += 8)
            tile[ty + i][tx] = W[(size_t)(k0 + ty + i) * C_ + n0 + tx];
        __syncthreads();
        #pragma unroll
        for (int i = 0; i < 32; i += 8) {
            int nl = ty + i;
            float v = tile[tx][nl];
            __nv_bfloat16 h = __float2bfloat16(v);
            __nv_bfloat16 l = __float2bfloat16(v - __bfloat162float(h));
            size_t o = ((size_t)w * C_ + (n0 + nl)) * C_ + k0 + tx;
            g_Wht[o] = h;
            g_Wlt[o] = l;
        }
    } else {
        // scales
        int ch = threadIdx.x;
        if (ch < NCHUNK) {
            const float step = 0.03f / 4095.0f;
            float r = 1.0f;
            for (int i = 0; i < CHUNK; ++i) {
                int t = ch * CHUNK + i;
                float g = 0.96f + step * (float)t;
                r *= g;
                g_sQ[t] = r;
                g_sK[t] = 1.0f / r;
            }
            g_SR[ch] = r;
        }
    }
}

// -------- HMMA projection v4: fused transpose epilogue for K/V (best-known, 749.7us cfg) --------
#define SA 40
#define TILE_HW (128 * SA)
#define PJ_TB   (TILE_HW * 2)
#define PJ_BUF  (4 * PJ_TB)
#define PJ_TRS  136
__global__ __launch_bounds__(256, 2) void projmma_kernel(
        const float* __restrict__ bQ, const float* __restrict__ bK,
        const float* __restrict__ bV) {
    extern __shared__ char shp[];
    const uint32_t sbase = smem_u32(shp);

    const int tid = threadIdx.x;
    const int w = tid >> 5, lane = tid & 31;
    const int g = lane >> 2, t4 = lane & 3;
    const int wm = w >> 2, wn = w & 3;
    const int which = blockIdx.x >> 2;
    const int n0 = (blockIdx.x & 3) * 128;
    const int m0 = blockIdx.y * 128;
    const float* bias = (which == 0) ? bQ : ((which == 1) ? bK : bV);

    const __nv_bfloat16* srcs[4] = {
        g_Xh + (size_t)m0 * C_, g_Xl + (size_t)m0 * C_,
        g_Wht + ((size_t)which * C_ + n0) * C_, g_Wlt + ((size_t)which * C_ + n0) * C_ };

    auto stage = [&](int bufi, int ck) {
        uint32_t base = sbase + (uint32_t)bufi * PJ_BUF;
        const int k0 = ck * 32;
        #pragma unroll
        for (int a = 0; a < 4; ++a) {
            #pragma unroll
            for (int j = 0; j < 2; ++j) {
                int u = tid + j * 256;
                int r = u >> 2, cg = u & 3;
                cpasync16(base + a * PJ_TB + r * 80 + cg * 16,
                          srcs[a] + (size_t)r * C_ + k0 + cg * 8);
            }
        }
    };

    float acc[4][4][4];
    #pragma unroll
    for (int i = 0; i < 4; ++i)
        #pragma unroll
        for (int j = 0; j < 4; ++j)
            #pragma unroll
            for (int r = 0; r < 4; ++r) acc[i][j][r] = 0.f;

    stage(0, 0);
    CP_COMMIT(); CP_WAIT0();
    __syncthreads();

    for (int ck = 0; ck < 16; ++ck) {
        const int buf = ck & 1;
        if (ck + 1 < 16) stage(buf ^ 1, ck + 1);
        CP_COMMIT();

        const uint32_t bAh = sbase + buf * PJ_BUF;
        const uint32_t bAl = bAh + PJ_TB;
        const uint32_t bBh = bAh + 2 * PJ_TB;
        const uint32_t bBl = bAh + 3 * PJ_TB;

        #pragma unroll
        for (int kk = 0; kk < 32; kk += 16) {
            uint32_t bhf[4], blf[4], bhf2[4], blf2[4];
            ldsm4(bhf,  addrB(bBh, wn * 32,      kk, SA, lane));
            ldsm4(bhf2, addrB(bBh, wn * 32 + 16, kk, SA, lane));
            ldsm4(blf,  addrB(bBl, wn * 32,      kk, SA, lane));
            ldsm4(blf2, addrB(bBl, wn * 32 + 16, kk, SA, lane));
            #pragma unroll
            for (int mf = 0; mf < 4; ++mf) {
                uint32_t ah[4], al[4];
                ldsm4(ah, addrA(bAh, wm * 64 + mf * 16, kk, SA, lane));
                ldsm4(al, addrA(bAl, wm * 64 + mf * 16, kk, SA, lane));
                mma16816(acc[mf][0], ah, bhf);      mma16816(acc[mf][0], ah, blf);
                mma16816(acc[mf][0], al, bhf);
                mma16816(acc[mf][1], ah, bhf + 2);  mma16816(acc[mf][1], ah, blf + 2);
                mma16816(acc[mf][1], al, bhf + 2);
                mma16816(acc[mf][2], ah, bhf2);     mma16816(acc[mf][2], ah, blf2);
                mma16816(acc[mf][2], al, bhf2);
                mma16816(acc[mf][3], ah, bhf2 + 2); mma16816(acc[mf][3], ah, blf2 + 2);
                mma16816(acc[mf][3], al, bhf2 + 2);
            }
        }
        CP_WAIT0();
        __syncthreads();
    }

    __nv_bfloat16* Th = (__nv_bfloat16*)shp;
    __nv_bfloat16* Tl = (__nv_bfloat16*)(shp + 128 * PJ_TRS * 2);

    #pragma unroll
    for (int mf = 0; mf < 4; ++mf) {
        int m = m0 + wm * 64 + mf * 16 + g;
        int tA = m & (T_ - 1);
        int tB = (m + 8) & (T_ - 1);
        float sA = (which == 0) ? g_sQ[tA] : ((which == 1) ? g_sK[tA] : 1.0f);
        float sB = (which == 0) ? g_sQ[tB] : ((which == 1) ? g_sK[tB] : 1.0f);
        #pragma unroll
        for (int nf = 0; nf < 4; ++nf) {
            int nl = wn * 32 + nf * 8 + 2 * t4;
            int n = n0 + nl;
            float2 bb = *(const float2*)&bias[n];
            float2 o0 = make_float2((acc[mf][nf][0] + bb.x) * sA,
                                    (acc[mf][nf][1] + bb.y) * sA);
            float2 o1 = make_float2((acc[mf][nf][2] + bb.x) * sB,
                                    (acc[mf][nf][3] + bb.y) * sB);
            size_t i0 = (size_t)m * C_ + n, i1 = (size_t)(m + 8) * C_ + n;
            if (which == 0) {
                split2(&g_Qh[i0], &g_Ql[i0], o0);
                split2(&g_Qh[i1], &g_Ql[i1], o1);
            } else {
                int ml = wm * 64 + mf * 16 + g;
                split2(&Th[ml * PJ_TRS + nl], &Tl[ml * PJ_TRS + nl], o0);
                split2(&Th[(ml + 8) * PJ_TRS + nl], &Tl[(ml + 8) * PJ_TRS + nl], o1);
                if (which == 1) {
                    split2(&g_Kh[i0], &g_Kl[i0], o0);
                    split2(&g_Kh[i1], &g_Kl[i1], o1);
                }
            }
        }
    }

    if (which != 0) {
        __syncthreads();
        __nv_bfloat16* dsth = (which == 1) ? g_KTh : g_VTh;
        __nv_bfloat16* dstl = (which == 1) ? g_KTl : g_VTl;
        const size_t bofs = (size_t)(m0 >> 12) * C_ * T_;
        const int tbase = m0 & (T_ - 1);
        const int cl = tid >> 1, seg = tid & 1;
        #pragma unroll
        for (int u = 0; u < 16; ++u) {
            int tl = seg * 64 + u * 4;
            __nv_bfloat16 hp[4], lp[4];
            #pragma unroll
            for (int e = 0; e < 4; ++e) {
                hp[e] = Th[(tl + e) * PJ_TRS + cl];
                lp[e] = Tl[(tl + e) * PJ_TRS + cl];
            }
            size_t o = bofs + (size_t)(n0 + cl) * T_ + tbase + tl;
            *(uint2*)&dsth[o] = *(uint2*)hp;
            *(uint2*)&dstl[o] = *(uint2*)lp;
        }
    }
}

// -------- local masked attention via HMMA + ldmatrix (best-known cfg) --------
#define L_TILE 9216
#define L_BUF  (4 * L_TILE)
#define L_ASH  (2 * L_BUF)
#define L_ASL  (L_ASH + L_TILE)
#define L_SMEM (L_ASL + L_TILE)
__global__ __launch_bounds__(256, 2) void localmma_kernel() {
    extern __shared__ char shl[];
    const uint32_t sbase = smem_u32(shl);
    __nv_bfloat16* Ash = (__nv_bfloat16*)(shl + L_ASH);
    __nv_bfloat16* Asl = (__nv_bfloat16*)(shl + L_ASL);
    const uint32_t aAsh = sbase + L_ASH, aAsl = sbase + L_ASL;

    const int tid = threadIdx.x;
    const int w = tid >> 5, lane = tid & 31;
    const int g = lane >> 2, t4 = lane & 3;
    const int wm = w >> 2, wn = w & 3;
    const int b = blockIdx.x >> 6;
    const int ch = blockIdx.x & 63;
    const size_t rowbase = (size_t)b * T_ + (size_t)ch * CHUNK;

    const __nv_bfloat16* qkSrc[4] = {
        g_Qh + rowbase * C_, g_Ql + rowbase * C_,
        g_Kh + rowbase * C_, g_Kl + rowbase * C_ };
    const __nv_bfloat16* VThb = g_VTh + (size_t)b * C_ * T_;
    const __nv_bfloat16* VTlb = g_VTl + (size_t)b * C_ * T_;

    auto stage_qk = [&](int bufi, int ck2) {
        uint32_t base = sbase + (uint32_t)bufi * L_BUF;
        #pragma unroll
        for (int a = 0; a < 4; ++a) {
            #pragma unroll
            for (int j = 0; j < 2; ++j) {
                int u = tid + j * 256;
                int row = u >> 3, c8 = u & 7;
                cpasync16(base + a * L_TILE + row * 144 + c8 * 16,
                          qkSrc[a] + (size_t)row * C_ + ck2 * 64 + c8 * 8);
            }
        }
    };
    auto stage_vt = [&](int bufi, int dt) {
        uint32_t base = sbase + (uint32_t)bufi * L_BUF;
        #pragma unroll
        for (int hl = 0; hl < 2; ++hl) {
            const __nv_bfloat16* src = hl ? VTlb : VThb;
            #pragma unroll
            for (int j = 0; j < 4; ++j) {
                int u = tid + j * 256;
                int row = u >> 3, c8 = u & 7;
                cpasync16(base + hl * (2 * L_TILE) + row * 144 + c8 * 16,
                          src + (size_t)(dt * 128 + row) * T_ + ch * CHUNK + c8 * 8);
            }
        }
    };

    float acc[2][2][4];
    #pragma unroll
    for (int i = 0; i < 2; ++i)
        #pragma unroll
        for (int j = 0; j < 2; ++j)
            #pragma unroll
            for (int r = 0; r < 4; ++r) acc[i][j][r] = 0.f;

    stage_qk(0, 0);
    CP_COMMIT(); CP_WAIT0();
    __syncthreads();

    for (int ck2 = 0; ck2 < 8; ++ck2) {
        const int buf = ck2 & 1;
        if (ck2 + 1 < 8) stage_qk(buf ^ 1, ck2 + 1);
        CP_COMMIT();
        const uint32_t bQh = sbase + buf * L_BUF;
        const uint32_t bQl = bQh + L_TILE;
        const uint32_t bKh = bQh + 2 * L_TILE;
        const uint32_t bKl = bQh + 3 * L_TILE;
        #pragma unroll
        for (int kk = 0; kk < 64; kk += 16) {
            uint32_t bh[4], bl[4];
            ldsm4(bh, addrB(bKh, wn * 16, kk, 72, lane));
            ldsm4(bl, addrB(bKl, wn * 16, kk, 72, lane));
            #pragma unroll
            for (int mf = 0; mf < 2; ++mf) {
                uint32_t ah[4], al[4];
                ldsm4(ah, addrA(bQh, wm * 32 + mf * 16, kk, 72, lane));
                ldsm4(al, addrA(bQl, wm * 32 + mf * 16, kk, 72, lane));
                mma16816(acc[mf][0], ah, bh);     mma16816(acc[mf][0], ah, bl);
                mma16816(acc[mf][0], al, bh);
                mma16816(acc[mf][1], ah, bh + 2); mma16816(acc[mf][1], ah, bl + 2);
                mma16816(acc[mf][1], al, bh + 2);
            }
        }
        CP_WAIT0();
        __syncthreads();
    }

    #pragma unroll
    for (int mf = 0; mf < 2; ++mf) {
        #pragma unroll
        for (int nf = 0; nf < 2; ++nf) {
            int t0r = wm * 32 + mf * 16 + g;
            int s0 = wn * 16 + nf * 8 + 2 * t4;
            #pragma unroll
            for (int e = 0; e < 4; ++e) {
                int tt = t0r + (e >> 1) * 8;
                int ss = s0 + (e & 1);
                float v = (ss <= tt) ? acc[mf][nf][e] : 0.f;
                __nv_bfloat16 h = __float2bfloat16(v);
                Ash[tt * 72 + ss] = h;
                Asl[tt * 72 + ss] = __float2bfloat16(v - __bfloat162float(h));
            }
        }
    }
    __syncthreads();

    stage_vt(0, 0);
    CP_COMMIT(); CP_WAIT0();
    __syncthreads();

    for (int dt = 0; dt < 4; ++dt) {
        const int buf = dt & 1;
        if (dt + 1 < 4) stage_vt(buf ^ 1, dt + 1);
        CP_COMMIT();
        const uint32_t bVh = sbase + buf * L_BUF;
        const uint32_t bVl = bVh + 2 * L_TILE;

        float acc2[2][4][4];
        #pragma unroll
        for (int i = 0; i < 2; ++i)
            #pragma unroll
            for (int j = 0; j < 4; ++j)
                #pragma unroll
                for (int r = 0; r < 4; ++r) acc2[i][j][r] = 0.f;

        #pragma unroll
        for (int kk = 0; kk < 64; kk += 16) {
            uint32_t bh[4], bl[4], bh2[4], bl2[4];
            ldsm4(bh,  addrB(bVh, wn * 32,      kk, 72, lane));
            ldsm4(bh2, addrB(bVh, wn * 32 + 16, kk, 72, lane));
            ldsm4(bl,  addrB(bVl, wn * 32,      kk, 72, lane));
            ldsm4(bl2, addrB(bVl, wn * 32 + 16, kk, 72, lane));
            #pragma unroll
            for (int mf = 0; mf < 2; ++mf) {
                uint32_t ah[4], al[4];
                ldsm4(ah, addrA(aAsh, wm * 32 + mf * 16, kk, 72, lane));
                ldsm4(al, addrA(aAsl, wm * 32 + mf * 16, kk, 72, lane));
                mma16816(acc2[mf][0], ah, bh);      mma16816(acc2[mf][0], ah, bl);
                mma16816(acc2[mf][0], al, bh);
                mma16816(acc2[mf][1], ah, bh + 2);  mma16816(acc2[mf][1], ah, bl + 2);
                mma16816(acc2[mf][1], al, bh + 2);
                mma16816(acc2[mf][2], ah, bh2);     mma16816(acc2[mf][2], ah, bl2);
                mma16816(acc2[mf][2], al, bh2);
                mma16816(acc2[mf][3], ah, bh2 + 2); mma16816(acc2[mf][3], ah, bl2 + 2);
                mma16816(acc2[mf][3], al, bh2 + 2);
            }
        }

        #pragma unroll
        for (int mf = 0; mf < 2; ++mf) {
            int tt = wm * 32 + mf * 16 + g;
            #pragma unroll
            for (int nf = 0; nf < 4; ++nf) {
                int d = dt * 128 + wn * 32 + nf * 8 + 2 * t4;
                *(float2*)&g_OL[(rowbase + tt) * C_ + d] =
                    make_float2(acc2[mf][nf][0], acc2[mf][nf][1]);
                *(float2*)&g_OL[(rowbase + tt + 8) * C_ + d] =
                    make_float2(acc2[mf][nf][2], acc2[mf][nf][3]);
            }
        }
        CP_WAIT0();
        __syncthreads();
    }
}

// ---------------- scan v7b (best-known cfg): 512 threads, split-k GEMM1 + split-c GEMM2 ----------------
#define S5_SH    0
#define S5_SL    16640
#define S5_STG   33280
#define S5_TILE  36864
#define S5_BUFSZ (2 * S5_TILE)
#define S5_VT    (S5_STG + 2 * S5_BUFSZ)
#define S5_RED   (S5_VT + 4608)
#define S5_SMEM  (S5_RED + 4096)

__global__ __launch_bounds__(512) void scan7_kernel(
        float* __restrict__ O, float* __restrict__ Sout, int writeS) {
    extern __shared__ char s5[];
    __nv_bfloat16* SHh = (__nv_bfloat16*)(s5 + S5_SH);
    __nv_bfloat16* SHl = (__nv_bfloat16*)(s5 + S5_SL);
    float* RED = (float*)(s5 + S5_RED);
    const uint32_t sbase = smem_u32(s5);
    const uint32_t aSHh = sbase + S5_SH, aSHl = sbase + S5_SL;

    const int tid = threadIdx.x;
    const int w = tid >> 5, lane = tid & 31;
    const int g = lane >> 2, t4 = lane & 3;
    const int w8 = w & 7, khalf = w >> 3;
    const int mg = w8 >> 1, ng = w8 & 1;
    const int b = blockIdx.x >> 5;
    const int d0 = (blockIdx.x & 31) * 16;

    const __nv_bfloat16* Qh  = g_Qh  + (size_t)b * T_ * C_;
    const __nv_bfloat16* Ql  = g_Ql  + (size_t)b * T_ * C_;
    const __nv_bfloat16* KTh = g_KTh + (size_t)b * C_ * T_;
    const __nv_bfloat16* KTl = g_KTl + (size_t)b * C_ * T_;
    const __nv_bfloat16* VTh = g_VTh + (size_t)b * C_ * T_;
    const __nv_bfloat16* VTl = g_VTl + (size_t)b * C_ * T_;
    const float* OLb = g_OL + (size_t)b * T_ * C_;
    float* Ob = O + (size_t)b * T_ * C_;

    for (int i = tid; i < 16 * 520 / 2; i += 512) {
        ((uint32_t*)SHh)[i] = 0u;
        ((uint32_t*)SHl)[i] = 0u;
    }

    auto stage_q = [&](int bufi, size_t rb, int half) {
        uint32_t base = sbase + S5_STG + (uint32_t)bufi * S5_BUFSZ;
        #pragma unroll
        for (int j = 0; j < 8; ++j) {
            int u = tid + 512 * j;
            int hl = u >> 11, ur = u & 2047;
            int row = ur >> 5, c16 = ur & 31;
            const __nv_bfloat16* src = hl ? Ql : Qh;
            cpasync16(base + (uint32_t)hl * S5_TILE + row * 528 + c16 * 16,
                      src + (rb + row) * C_ + half * 256 + c16 * 8);
        }
    };
    auto stage_k = [&](int bufi, size_t rb, int half) {
        uint32_t base = sbase + S5_STG + (uint32_t)bufi * S5_BUFSZ;
        #pragma unroll
        for (int j = 0; j < 8; ++j) {
            int u = tid + 512 * j;
            int hl = u >> 11, ur = u & 2047;
            int row = ur >> 3, c8 = ur & 7;
            const __nv_bfloat16* src = hl ? KTl : KTh;
            cpasync16(base + (uint32_t)hl * S5_TILE + row * 144 + c8 * 16,
                      src + (size_t)(half * 256 + row) * T_ + rb + c8 * 8);
        }
    };
    auto stage_vt = [&](size_t rb) {
        if (tid < 256) {
            int hl = tid >> 7, ur = tid & 127;
            int row = ur >> 3, c8 = ur & 7;
            const __nv_bfloat16* src = hl ? VTl : VTh;
            cpasync16(sbase + S5_VT + hl * 2304 + row * 144 + c8 * 16,
                      src + (size_t)(d0 + row) * T_ + rb + c8 * 8);
        }
    };

    stage_q(0, 0, 0);
    CP_COMMIT(); CP_WAIT0();
    __syncthreads();

    float acc1a[4] = {0.f, 0.f, 0.f, 0.f};
    float acc1b[4] = {0.f, 0.f, 0.f, 0.f};
    float2 ol0 = make_float2(0.f, 0.f), ol1 = make_float2(0.f, 0.f);
    float Sreg[16];
    #pragma unroll
    for (int i = 0; i < 16; ++i) Sreg[i] = 0.f;

    for (int ch = 0; ch < NCHUNK; ++ch) {
        const size_t crow = (size_t)ch * CHUNK;
        const float R = __ldg(&g_SR[ch]);

        for (int p = 0; p < 4; ++p) {
            const int buf = p & 1, nbuf = buf ^ 1;
            if (p == 0) {
                stage_q(nbuf, crow, 1);
                if (khalf == 0) {
                    ol0 = __ldg((const float2*)&OLb[(crow + mg * 16 + g) * C_ + d0 + ng * 8 + 2 * t4]);
                    ol1 = __ldg((const float2*)&OLb[(crow + mg * 16 + g + 8) * C_ + d0 + ng * 8 + 2 * t4]);
                }
            } else if (p == 1) {
                stage_k(nbuf, crow, 0);
                stage_vt(crow);
            } else if (p == 2) {
                stage_k(nbuf, crow, 1);
            } else {
                size_t nrow = (ch + 1 < NCHUNK) ? crow + CHUNK : crow;
                stage_q(nbuf, nrow, 0);
            }
            CP_COMMIT();

            if (p < 2) {
                const uint32_t bQsh = sbase + S5_STG + buf * S5_BUFSZ;
                const uint32_t bQsl = bQsh + S5_TILE;
                #pragma unroll
                for (int kk = 0; kk < 128; kk += 32) {
                    const int kloc = khalf * 128 + kk;
                    uint32_t bh4[4], bl4[4];
                    ldsm4(bh4, addrBK(aSHh, ng * 8, p * 256 + kloc, 520, lane));
                    ldsm4(bl4, addrBK(aSHl, ng * 8, p * 256 + kloc, 520, lane));
                    #pragma unroll
                    for (int s = 0; s < 2; ++s) {
                        float* a1 = s ? acc1b : acc1a;
                        uint32_t ah[4], al[4];
                        ldsm4(ah, addrA(bQsh, mg * 16, kloc + s * 16, 264, lane));
                        ldsm4(al, addrA(bQsl, mg * 16, kloc + s * 16, 264, lane));
                        mma16816(a1, ah, bh4 + 2 * s);
                        mma16816(a1, ah, bl4 + 2 * s);
                        mma16816(a1, al, bh4 + 2 * s);
                    }
                }
                if (p == 1 && khalf == 1) {
                    *(float4*)&RED[(w8 * 32 + lane) * 4] =
                        make_float4(acc1a[0] + acc1b[0], acc1a[1] + acc1b[1],
                                    acc1a[2] + acc1b[2], acc1a[3] + acc1b[3]);
                    #pragma unroll
                    for (int r = 0; r < 4; ++r) { acc1a[r] = 0.f; acc1b[r] = 0.f; }
                }
            } else {
                if (p == 2 && khalf == 0) {
                    float4 pr = *(const float4*)&RED[(w8 * 32 + lane) * 4];
                    const int trow = (int)crow + mg * 16 + g;
                    const int d = d0 + ng * 8 + 2 * t4;
                    *(float2*)&Ob[(size_t)trow * C_ + d] =
                        make_float2(tanhf(acc1a[0] + acc1b[0] + pr.x + ol0.x),
                                    tanhf(acc1a[1] + acc1b[1] + pr.y + ol0.y));
                    *(float2*)&Ob[(size_t)(trow + 8) * C_ + d] =
                        make_float2(tanhf(acc1a[2] + acc1b[2] + pr.z + ol1.x),
                                    tanhf(acc1a[3] + acc1b[3] + pr.w + ol1.y));
                    #pragma unroll
                    for (int r = 0; r < 4; ++r) { acc1a[r] = 0.f; acc1b[r] = 0.f; }
                }
                const uint32_t bKsh = sbase + S5_STG + buf * S5_BUFSZ;
                const uint32_t bKsl = bKsh + S5_TILE;
                const uint32_t bVth = sbase + S5_VT;
                const uint32_t bVtl = bVth + 2304;
                float acc2[2][4];
                #pragma unroll
                for (int j = 0; j < 2; ++j)
                    #pragma unroll
                    for (int r = 0; r < 4; ++r) acc2[j][r] = 0.f;
                #pragma unroll
                for (int kk = 0; kk < 64; kk += 16) {
                    uint32_t bh[4], bl[4];
                    ldsm4(bh, addrB(bVth, 0, kk, 72, lane));
                    ldsm4(bl, addrB(bVtl, 0, kk, 72, lane));
                    uint32_t ah[4], al[4];
                    ldsm4(ah, addrA(bKsh, w * 16, kk, 72, lane));
                    ldsm4(al, addrA(bKsl, w * 16, kk, 72, lane));
                    mma16816(acc2[0], ah, bh);     mma16816(acc2[0], ah, bl);
                    mma16816(acc2[0], al, bh);
                    mma16816(acc2[1], ah, bh + 2); mma16816(acc2[1], ah, bl + 2);
                    mma16816(acc2[1], al, bh + 2);
                }
                const int pi = p - 2;
                const int cb = pi * 256 + w * 16;
                #pragma unroll
                for (int nf = 0; nf < 2; ++nf) {
                    #pragma unroll
                    for (int e = 0; e < 4; ++e) {
                        int idx = (pi * 2 + nf) * 4 + e;
                        int c = cb + g + (e >> 1) * 8;
                        int d = nf * 8 + 2 * t4 + (e & 1);
                        int ad = d * 520 + c;
                        float v = (Sreg[idx] + acc2[nf][e]) * R;
                        Sreg[idx] = v;
                        __nv_bfloat16 h = __float2bfloat16(v);
                        SHh[ad] = h;
                        SHl[ad] = __float2bfloat16(v - __bfloat162float(h));
                    }
                }
            }
            CP_WAIT0();
            __syncthreads();
        }
    }

    if (writeS) {
        for (int idx = tid; idx < C_ * 16; idx += 512) {
            int c = idx >> 4, dl = idx & 15;
            Sout[((size_t)b * C_ + c) * C_ + d0 + dl] =
                __bfloat162float(SHh[dl * 520 + c]) + __bfloat162float(SHl[dl * 520 + c]);
        }
    }
}

extern "C" void kernel_launch(void* const* d_in, const int* in_sizes, int n_in,
                              void* d_out, int out_size) {
    const float* X  = (const float*)d_in[0];
    // d_in[1] = S_n (ignored; reference resets state to zero)
    const float* WQ = (const float*)d_in[2];
    const float* bQ = (const float*)d_in[3];
    const float* WK = (const float*)d_in[4];
    const float* bK = (const float*)d_in[5];
    const float* WV = (const float*)d_in[6];
    const float* bV = (const float*)d_in[7];
    float* out = (float*)d_out;

    const int oElems = B_ * T_ * C_;
    const int sElems = B_ * C_ * C_;
    int writeS = (out_size >= oElems + sElems) ? 1 : 0;
    float* Sout = out + oElems;

    const int smP = 2 * PJ_BUF;
    cudaFuncSetAttribute(projmma_kernel, cudaFuncAttributeMaxDynamicSharedMemorySize, smP);
    cudaFuncSetAttribute(localmma_kernel, cudaFuncAttributeMaxDynamicSharedMemorySize, L_SMEM);
    cudaFuncSetAttribute(scan7_kernel, cudaFuncAttributeMaxDynamicSharedMemorySize, S5_SMEM);

    prep_kernel<<<8961, 256>>>(X, WQ, WK, WV);
    dim3 pg(12, (B_ * T_) / 128);
    projmma_kernel<<<pg, 256, smP>>>(bQ, bK, bV);
    localmma_kernel<<<B_ * NCHUNK, 256, L_SMEM>>>();
    scan7_kernel<<<B_ * 32, 512, S5_SMEM>>>(out, Sout, writeS);
}